// round 3
// baseline (speedup 1.0000x reference)
#include <cuda_runtime.h>
#include <cuda_bf16.h>

// QuantumLSTMCell — analytic collapse of the quantum circuit.
// <Z_0> after the CNOT chain equals cos(theta[0]) * cos(ang[:,0]) because
// Z_0 commutes with every CNOT in the chain (wire 0 is only ever a control)
// and the pre-CNOT state is a product state. Only row 0 of each W and
// element 0 of each bias/theta contribute.
//
// B=16384, D=256, H=1024, comb dim = 1280.

#define B_ROWS 16384
#define D_DIM  256
#define H_DIM  1024
#define COMB   1280
#define TPB    256

__device__ __forceinline__ float sigmoidf_(float v) {
    return 1.0f / (1.0f + expf(-v));
}

__global__ __launch_bounds__(TPB)
void qlstm_kernel(
    const float* __restrict__ x,   // [B, 256]
    const float* __restrict__ hx,  // [B, 1024]
    const float* __restrict__ cx,  // [B, 1024]
    const float* __restrict__ Wf, const float* __restrict__ bf,
    const float* __restrict__ Wi, const float* __restrict__ bi,
    const float* __restrict__ Wg, const float* __restrict__ bg,
    const float* __restrict__ Wo, const float* __restrict__ bo,
    const float* __restrict__ thf, const float* __restrict__ thi,
    const float* __restrict__ thg, const float* __restrict__ tho,
    float* __restrict__ out_h,     // [B, 1024]
    float* __restrict__ out_c)     // [B, 1024]
{
    const int b = blockIdx.x;
    const int t = threadIdx.x;
    const int lane = t & 31;
    const int warp = t >> 5;

    const float* xr = x  + (size_t)b * D_DIM;
    const float* hr = hx + (size_t)b * H_DIM;

    // ---- Phase 1: 4 dot products over comb = [x | hx] (row 0 of each W) ----
    float pf, pi, pg, po;
    {
        float v = xr[t];                       // i = t in [0,256)
        pf = v * __ldg(&Wf[t]);
        pi = v * __ldg(&Wi[t]);
        pg = v * __ldg(&Wg[t]);
        po = v * __ldg(&Wo[t]);
    }
    #pragma unroll
    for (int k = 0; k < 4; k++) {              // i = 256 + t + k*256
        int j = t + k * 256;                   // hx index
        float v = hr[j];
        pf += v * __ldg(&Wf[256 + j]);
        pi += v * __ldg(&Wi[256 + j]);
        pg += v * __ldg(&Wg[256 + j]);
        po += v * __ldg(&Wo[256 + j]);
    }

    // warp reduce (4 values)
    #pragma unroll
    for (int off = 16; off > 0; off >>= 1) {
        pf += __shfl_down_sync(0xffffffffu, pf, off);
        pi += __shfl_down_sync(0xffffffffu, pi, off);
        pg += __shfl_down_sync(0xffffffffu, pg, off);
        po += __shfl_down_sync(0xffffffffu, po, off);
    }

    __shared__ float sred[4][8];
    __shared__ float gate[4];
    if (lane == 0) {
        sred[0][warp] = pf;
        sred[1][warp] = pi;
        sred[2][warp] = pg;
        sred[3][warp] = po;
    }
    __syncthreads();

    if (t == 0) {
        float sf = 0.f, si = 0.f, sg = 0.f, so = 0.f;
        #pragma unroll
        for (int w = 0; w < 8; w++) {
            sf += sred[0][w]; si += sred[1][w];
            sg += sred[2][w]; so += sred[3][w];
        }
        float af = sf + __ldg(&bf[0]);
        float ai = si + __ldg(&bi[0]);
        float ag = sg + __ldg(&bg[0]);
        float ao = so + __ldg(&bo[0]);
        gate[0] = sigmoidf_(cosf(__ldg(&thf[0])) * cosf(af));
        gate[1] = sigmoidf_(cosf(__ldg(&thi[0])) * cosf(ai));
        gate[2] = tanhf   (cosf(__ldg(&thg[0])) * cosf(ag));
        gate[3] = sigmoidf_(cosf(__ldg(&tho[0])) * cosf(ao));
    }
    __syncthreads();

    // ---- Phase 2: elementwise LSTM update, float4 (1024/4 = 256 = TPB) ----
    const float fg = gate[0];
    const float ig = gate[1];
    const float gg = gate[2];
    const float og = gate[3];
    const float ig_gg = ig * gg;

    const float4* c4  = (const float4*)(cx    + (size_t)b * H_DIM);
    float4*       h4o = (float4*)      (out_h + (size_t)b * H_DIM);
    float4*       c4o = (float4*)      (out_c + (size_t)b * H_DIM);

    float4 cv = c4[t];
    float4 nc, nh;
    nc.x = fg * cv.x + ig_gg;
    nc.y = fg * cv.y + ig_gg;
    nc.z = fg * cv.z + ig_gg;
    nc.w = fg * cv.w + ig_gg;
    nh.x = og * tanhf(nc.x);
    nh.y = og * tanhf(nc.y);
    nh.z = og * tanhf(nc.z);
    nh.w = og * tanhf(nc.w);
    c4o[t] = nc;
    h4o[t] = nh;
}

extern "C" void kernel_launch(void* const* d_in, const int* in_sizes, int n_in,
                              void* d_out, int out_size) {
    // metadata order: x, hx, cx, Wf, bf, Wi, bi, Wg, bg, Wo, bo,
    //                 theta_f, theta_i, theta_g, theta_o
    const float* x   = (const float*)d_in[0];
    const float* hx  = (const float*)d_in[1];
    const float* cx  = (const float*)d_in[2];
    const float* Wf  = (const float*)d_in[3];
    const float* bf  = (const float*)d_in[4];
    const float* Wi  = (const float*)d_in[5];
    const float* bi  = (const float*)d_in[6];
    const float* Wg  = (const float*)d_in[7];
    const float* bg  = (const float*)d_in[8];
    const float* Wo  = (const float*)d_in[9];
    const float* bo  = (const float*)d_in[10];
    const float* thf = (const float*)d_in[11];
    const float* thi = (const float*)d_in[12];
    const float* thg = (const float*)d_in[13];
    const float* tho = (const float*)d_in[14];

    float* out   = (float*)d_out;
    float* out_h = out;                                   // new_h first
    float* out_c = out + (size_t)B_ROWS * H_DIM;          // new_c second

    qlstm_kernel<<<B_ROWS, TPB>>>(x, hx, cx,
                                  Wf, bf, Wi, bi, Wg, bg, Wo, bo,
                                  thf, thi, thg, tho,
                                  out_h, out_c);
}